// round 10
// baseline (speedup 1.0000x reference)
#include <cuda_runtime.h>
#include <cuda_bf16.h>
#include <cstdint>

// NCCLayer argmax: bf16 3-way-split HMMA + exact-margin rescue.
// R9 had rel_err 2.47e-3 = ~2 argmax flips from ~1e-6 split-MMA noise on
// sub-1e-6 margins. Fix: track top-2 approx values per row; rows with
// margin < 2*delta are re-decided by a rescue kernel running the VERBATIM
// R5 fp32 chain (measured bitwise-accepted, rel_err 0.0). Margin test is
// conservative (delta=1e-5 >> true ~1e-6 bound) => provably correct rows
// emitted directly, ambiguous rows (expected ~100-500) rescued exactly.

#define KK    16
#define DD    1024
#define NTOT  131072
#define TPB   256          // 8 warps, 128 n-rows per CTA
#define NBLK  (NTOT / 128)
#define MARGIN 2e-5f

__device__ __nv_bfloat16 g_as[3][NTOT * KK];   // A splits, n-major
__device__ __nv_bfloat16 g_bs[3][DD * KK];     // B splits, frag-packed (see prep_b)
__device__ int g_nflag;
__device__ int g_flaglist[NTOT];

// ---------------- prep: normalize + 3-way bf16 split ----------------
__device__ __forceinline__ void split3(float v, __nv_bfloat16& h1,
                                       __nv_bfloat16& h2, __nv_bfloat16& h3) {
    h1 = __float2bfloat16(v);
    float r1 = v - __bfloat162float(h1);
    h2 = __float2bfloat16(r1);
    float r2 = r1 - __bfloat162float(h2);
    h3 = __float2bfloat16(r2);
}

__global__ __launch_bounds__(256) void prep_a_kernel(const float* __restrict__ x) {
    const int n = blockIdx.x * 256 + threadIdx.x;
    float a[KK];
    float s = 0.f;
    #pragma unroll
    for (int k = 0; k < KK; ++k) { a[k] = x[k * NTOT + n]; s += a[k]; }
    const float mu = s * (1.0f / KK);
    float ss = 0.f;
    #pragma unroll
    for (int k = 0; k < KK; ++k) { a[k] -= mu; ss += a[k] * a[k]; }
    const float inv = 1.0f / (sqrtf(ss) + 1e-10f);
    #pragma unroll
    for (int k = 0; k < KK; ++k) {
        __nv_bfloat16 h1, h2, h3;
        split3(a[k] * inv, h1, h2, h3);
        g_as[0][n * KK + k] = h1;
        g_as[1][n * KK + k] = h2;
        g_as[2][n * KK + k] = h3;
    }
}

__global__ __launch_bounds__(256) void prep_b_kernel(const float* __restrict__ cmat) {
    if (blockIdx.x == 0 && threadIdx.x == 0) g_nflag = 0;  // reset per replay
    const int d = blockIdx.x * 256 + threadIdx.x;
    float b[KK];
    float s = 0.f;
    #pragma unroll
    for (int k = 0; k < KK; ++k) { b[k] = cmat[k * DD + d]; s += b[k]; }
    const float mu = s * (1.0f / KK);
    float ss = 0.f;
    #pragma unroll
    for (int k = 0; k < KK; ++k) { b[k] -= mu; ss += b[k] * b[k]; }
    const float inv = 1.0f / (sqrtf(ss) + 1e-10f);
    #pragma unroll
    for (int k = 0; k < KK; ++k) {
        __nv_bfloat16 h1, h2, h3;
        split3(b[k] * inv, h1, h2, h3);
        // frag-packed layout: for pair p (=0..3), slots {2p, 2p+1, 2p+8, 2p+9}
        // => one LDS.64 per split per thread in the hot loop.
        const int p    = (k & 7) >> 1;
        const int slot = ((k >> 3) << 1) | (k & 1);
        const int idx  = d * KK + p * 4 + slot;
        g_bs[0][idx] = h1;
        g_bs[1][idx] = h2;
        g_bs[2][idx] = h3;
    }
}

// ---------------- main: HMMA sweep + top-2 margin argmax ----------------
__device__ __forceinline__ void mma16816(float& d0, float& d1, float& d2, float& d3,
                                         uint32_t a0, uint32_t a1, uint32_t a2,
                                         uint32_t a3, uint32_t b0, uint32_t b1) {
    asm volatile(
        "mma.sync.aligned.m16n8k16.row.col.f32.bf16.bf16.f32 "
        "{%0,%1,%2,%3}, {%4,%5,%6,%7}, {%8,%9}, {%0,%1,%2,%3};"
        : "+f"(d0), "+f"(d1), "+f"(d2), "+f"(d3)
        : "r"(a0), "r"(a1), "r"(a2), "r"(a3), "r"(b0), "r"(b1));
}

__global__ __launch_bounds__(TPB) void ncc_hmma_kernel(float* __restrict__ out)
{
    extern __shared__ char smem[];   // B: 3 splits x 32 KB = 96 KB

    const int tid = threadIdx.x;
    const int wid = tid >> 5;
    const int lid = tid & 31;
    const int t   = lid & 3;    // quad pos
    const int r   = lid >> 2;   // group row / B col

    // ---- Stage all of B into shared (bulk uint4 copy, layout-agnostic) ----
    {
        const uint4* src = (const uint4*)&g_bs[0][0];
        uint4* dst = (uint4*)smem;
        #pragma unroll
        for (int i = 0; i < (3 * DD * KK * 2) / 16 / TPB; ++i)
            dst[tid + i * TPB] = src[tid + i * TPB];
    }
    __syncthreads();

    // ---- A fragments (rows n0 = base+r, n1 = n0+8), 3 splits ----
    const int nbase = blockIdx.x * 128 + wid * 16;
    const int n0 = nbase + r;
    const int n1 = n0 + 8;
    uint32_t af[3][4];
    #pragma unroll
    for (int s = 0; s < 3; ++s) {
        af[s][0] = *(const uint32_t*)&g_as[s][n0 * KK + 2 * t];
        af[s][1] = *(const uint32_t*)&g_as[s][n1 * KK + 2 * t];
        af[s][2] = *(const uint32_t*)&g_as[s][n0 * KK + 2 * t + 8];
        af[s][3] = *(const uint32_t*)&g_as[s][n1 * KK + 2 * t + 8];
    }

    float best0 = -3.0e38f, sec0 = -3.0e38f;
    float best1 = -3.0e38f, sec1 = -3.0e38f;
    int   bi0 = 0, bi1 = 0;

    // two accumulation chains for ILP: small terms, then big terms
    const int TIS[4] = {2, 1, 2, 0}, TJS[4] = {1, 2, 0, 2};
    const int TIB[4] = {1, 1, 0, 0}, TJB[4] = {1, 0, 1, 0};

    #pragma unroll 2
    for (int dtile = 0; dtile < DD / 8; ++dtile) {
        const int dg = dtile * 8;

        // B fragments: one LDS.64 per split (frag-packed layout)
        uint32_t bf[3][2];
        #pragma unroll
        for (int s = 0; s < 3; ++s) {
            const uint64_t q = *(const uint64_t*)(smem + s * (DD * KK * 2)
                                                  + (dg + r) * (KK * 2) + t * 8);
            bf[s][0] = (uint32_t)q;
            bf[s][1] = (uint32_t)(q >> 32);
        }

        float sA0 = 0.f, sA1 = 0.f, sA2 = 0.f, sA3 = 0.f;   // small chain
        float bA0 = 0.f, bA1 = 0.f, bA2 = 0.f, bA3 = 0.f;   // big chain
        #pragma unroll
        for (int q = 0; q < 4; ++q) {
            mma16816(sA0, sA1, sA2, sA3,
                     af[TIS[q]][0], af[TIS[q]][1], af[TIS[q]][2], af[TIS[q]][3],
                     bf[TJS[q]][0], bf[TJS[q]][1]);
            mma16816(bA0, bA1, bA2, bA3,
                     af[TIB[q]][0], af[TIB[q]][1], af[TIB[q]][2], af[TIB[q]][3],
                     bf[TJB[q]][0], bf[TJB[q]][1]);
        }
        const float v0 = bA0 + sA0, v1 = bA1 + sA1;
        const float v2 = bA2 + sA2, v3 = bA3 + sA3;

        const int c0 = dg + 2 * t, c1 = c0 + 1;
        // row n0: top-2 update
        {
            const float m01 = fmaxf(v0, v1), mn01 = fminf(v0, v1);
            if (m01 > best0) {
                sec0 = fmaxf(best0, mn01);
                best0 = m01;
                bi0 = (v0 >= v1) ? c0 : c1;
            } else {
                sec0 = fmaxf(sec0, m01);
            }
        }
        // row n1
        {
            const float m01 = fmaxf(v2, v3), mn01 = fminf(v2, v3);
            if (m01 > best1) {
                sec1 = fmaxf(best1, mn01);
                best1 = m01;
                bi1 = (v2 >= v3) ? c0 : c1;
            } else {
                sec1 = fmaxf(sec1, m01);
            }
        }
    }

    // ---- 4-lane butterfly reduce: (best desc, idx asc), track global second ----
    #pragma unroll
    for (int m = 1; m <= 2; m <<= 1) {
        float ob = __shfl_xor_sync(0xffffffffu, best0, m);
        float os = __shfl_xor_sync(0xffffffffu, sec0,  m);
        int   oi = __shfl_xor_sync(0xffffffffu, bi0,   m);
        float ns = fmaxf(fmaxf(fminf(best0, ob), sec0), os);
        if (ob > best0 || (ob == best0 && oi < bi0)) { best0 = ob; bi0 = oi; }
        sec0 = ns;

        ob = __shfl_xor_sync(0xffffffffu, best1, m);
        os = __shfl_xor_sync(0xffffffffu, sec1,  m);
        oi = __shfl_xor_sync(0xffffffffu, bi1,   m);
        ns = fmaxf(fmaxf(fminf(best1, ob), sec1), os);
        if (ob > best1 || (ob == best1 && oi < bi1)) { best1 = ob; bi1 = oi; }
        sec1 = ns;
    }

    if (t == 0) {
        out[n0] = (float)bi0;
        out[n1] = (float)bi1;
        if (best0 - sec0 < MARGIN) {       // ambiguous -> exact rescue
            const int j = atomicAdd(&g_nflag, 1);
            g_flaglist[j] = n0;
        }
        if (best1 - sec1 < MARGIN) {
            const int j = atomicAdd(&g_nflag, 1);
            g_flaglist[j] = n1;
        }
    }
}

// ---------------- rescue: verbatim R5 fp32 chain for flagged rows ----------------
__global__ __launch_bounds__(256) void rescue_kernel(
    const float* __restrict__ x,
    const float* __restrict__ cmat,
    float* __restrict__ out)
{
    const int warp  = (blockIdx.x * 256 + threadIdx.x) >> 5;
    const int lane  = threadIdx.x & 31;
    const int nwarp = (gridDim.x * 256) >> 5;
    const int count = g_nflag;

    for (int i = warp; i < count; i += nwarp) {
        const int n = g_flaglist[i];

        // a-normalization: identical op chain to the rel_err==0 R5 kernel
        float a[KK];
        float s = 0.f;
        #pragma unroll
        for (int k = 0; k < KK; ++k) { a[k] = x[k * NTOT + n]; s += a[k]; }
        const float mu = s * (1.0f / KK);
        float ss = 0.f;
        #pragma unroll
        for (int k = 0; k < KK; ++k) { a[k] -= mu; ss += a[k] * a[k]; }
        const float inv = 1.0f / (sqrtf(ss) + 1e-10f);
        #pragma unroll
        for (int k = 0; k < KK; ++k) a[k] *= inv;

        float best = -3.0e38f;
        int   bi   = 0;
        for (int d0 = 0; d0 < DD; d0 += 32) {
            const int d = d0 + lane;
            // b-normalization: identical op chain to R5
            float b[KK];
            float s2 = 0.f;
            #pragma unroll
            for (int k = 0; k < KK; ++k) { b[k] = cmat[k * DD + d]; s2 += b[k]; }
            const float mu2 = s2 * (1.0f / KK);
            float ss2 = 0.f;
            #pragma unroll
            for (int k = 0; k < KK; ++k) { b[k] -= mu2; ss2 += b[k] * b[k]; }
            const float inv2 = 1.0f / (sqrtf(ss2) + 1e-10f);
            float acc = 0.f;
            #pragma unroll
            for (int k = 0; k < KK; ++k) acc = fmaf(a[k], b[k] * inv2, acc);
            if (acc > best) { best = acc; bi = d; }   // ascending d per lane
        }
        // 32-lane reduce: (value desc, index asc) == first occurrence
        #pragma unroll
        for (int m = 16; m >= 1; m >>= 1) {
            const float ov = __shfl_xor_sync(0xffffffffu, best, m);
            const int   oi = __shfl_xor_sync(0xffffffffu, bi,   m);
            if (ov > best || (ov == best && oi < bi)) { best = ov; bi = oi; }
        }
        if (lane == 0) out[n] = (float)bi;
    }
}

extern "C" void kernel_launch(void* const* d_in, const int* in_sizes, int n_in,
                              void* d_out, int out_size)
{
    // Select inputs by element count — immune to metadata ordering.
    const float* x;
    const float* cmat;
    if (in_sizes[0] >= in_sizes[1]) {
        x    = (const float*)d_in[0];
        cmat = (const float*)d_in[1];
    } else {
        x    = (const float*)d_in[1];
        cmat = (const float*)d_in[0];
    }
    float* out = (float*)d_out;

    prep_b_kernel<<<DD / 256, 256>>>(cmat);
    prep_a_kernel<<<NTOT / 256, 256>>>(x);

    const int smem = 3 * DD * KK * 2;   // 96 KB
    cudaFuncSetAttribute(ncc_hmma_kernel,
                         cudaFuncAttributeMaxDynamicSharedMemorySize, smem);
    ncc_hmma_kernel<<<NBLK, TPB, smem>>>(out);

    rescue_kernel<<<256, 256>>>(x, cmat, out);
}

// round 11
// speedup vs baseline: 1.5490x; 1.5490x over previous
#include <cuda_runtime.h>
#include <cuda_bf16.h>
#include <cstdint>

// NCCLayer argmax: 2-way bf16 split HMMA (3 cross-term MMAs) + exact rescue.
// R10 validated the margin-rescue hybrid (rel_err 0.0) but HMMA legacy path
// costs ~16cyc/instr => cut 8 terms -> 3 (strict dot error <= 5e-5, margin
// 1.2e-4 > 2*delta). Rescue v2 uses precomputed fp32 bnorm (bitwise R5 chain,
// L2-resident) so flagged rows cost ~us, not 32us.

#define KK    16
#define DD    1024
#define NTOT  131072
#define TPB   256          // 8 warps, 128 n-rows per CTA
#define NBLK  (NTOT / 128)
#define MARGIN 1.2e-4f

__device__ __nv_bfloat16 g_as[2][NTOT * KK];   // A splits, n-major (8 MB)
__device__ __nv_bfloat16 g_bs[2][DD * KK];     // B splits, frag-packed (64 KB)
__device__ float g_bnorm[DD * KK];             // exact fp32 normalized b, [d][k]
__device__ int g_nflag;
__device__ int g_flaglist[NTOT];

// ---------------- prep: normalize + 2-way bf16 split ----------------
__device__ __forceinline__ void split2(float v, __nv_bfloat16& h1, __nv_bfloat16& h2) {
    h1 = __float2bfloat16(v);
    h2 = __float2bfloat16(v - __bfloat162float(h1));
}

__global__ __launch_bounds__(256) void prep_a_kernel(const float* __restrict__ x) {
    const int n = blockIdx.x * 256 + threadIdx.x;
    float a[KK];
    float s = 0.f;
    #pragma unroll
    for (int k = 0; k < KK; ++k) { a[k] = x[k * NTOT + n]; s += a[k]; }
    const float mu = s * (1.0f / KK);
    float ss = 0.f;
    #pragma unroll
    for (int k = 0; k < KK; ++k) { a[k] -= mu; ss += a[k] * a[k]; }
    const float inv = 1.0f / (sqrtf(ss) + 1e-10f);
    #pragma unroll
    for (int k = 0; k < KK; ++k) {
        __nv_bfloat16 h1, h2;
        split2(a[k] * inv, h1, h2);
        g_as[0][n * KK + k] = h1;
        g_as[1][n * KK + k] = h2;
    }
}

__global__ __launch_bounds__(256) void prep_b_kernel(const float* __restrict__ cmat) {
    if (blockIdx.x == 0 && threadIdx.x == 0) g_nflag = 0;  // reset per replay
    const int d = blockIdx.x * 256 + threadIdx.x;
    float b[KK];
    float s = 0.f;
    #pragma unroll
    for (int k = 0; k < KK; ++k) { b[k] = cmat[k * DD + d]; s += b[k]; }
    const float mu = s * (1.0f / KK);
    float ss = 0.f;
    #pragma unroll
    for (int k = 0; k < KK; ++k) { b[k] -= mu; ss += b[k] * b[k]; }
    const float inv = 1.0f / (sqrtf(ss) + 1e-10f);
    #pragma unroll
    for (int k = 0; k < KK; ++k) {
        const float bn = b[k] * inv;          // same op chain as R5 exact kernel
        g_bnorm[d * KK + k] = bn;
        __nv_bfloat16 h1, h2;
        split2(bn, h1, h2);
        // frag-packed: pair p = (k&7)>>1 holds slots {2p,2p+1,2p+8,2p+9}
        // => one LDS.64 per split per thread in the hot loop.
        const int p    = (k & 7) >> 1;
        const int slot = ((k >> 3) << 1) | (k & 1);
        const int idx  = d * KK + p * 4 + slot;
        g_bs[0][idx] = h1;
        g_bs[1][idx] = h2;
    }
}

// ---------------- main: 3-term HMMA sweep + branchless top-2 ----------------
__device__ __forceinline__ void mma16816(float& d0, float& d1, float& d2, float& d3,
                                         uint32_t a0, uint32_t a1, uint32_t a2,
                                         uint32_t a3, uint32_t b0, uint32_t b1) {
    asm volatile(
        "mma.sync.aligned.m16n8k16.row.col.f32.bf16.bf16.f32 "
        "{%0,%1,%2,%3}, {%4,%5,%6,%7}, {%8,%9}, {%0,%1,%2,%3};"
        : "+f"(d0), "+f"(d1), "+f"(d2), "+f"(d3)
        : "r"(a0), "r"(a1), "r"(a2), "r"(a3), "r"(b0), "r"(b1));
}

__global__ __launch_bounds__(TPB) void ncc_hmma_kernel(float* __restrict__ out)
{
    extern __shared__ char smem[];   // B: 2 splits x 32 KB = 64 KB

    const int tid = threadIdx.x;
    const int wid = tid >> 5;
    const int lid = tid & 31;
    const int t   = lid & 3;    // quad pos
    const int r   = lid >> 2;   // group row / B col

    // ---- Stage B into shared (bulk uint4 copy) ----
    {
        const uint4* src = (const uint4*)&g_bs[0][0];
        uint4* dst = (uint4*)smem;
        #pragma unroll
        for (int i = 0; i < (2 * DD * KK * 2) / 16 / TPB; ++i)
            dst[tid + i * TPB] = src[tid + i * TPB];
    }
    __syncthreads();

    // ---- A fragments (rows n0 = base+r, n1 = n0+8), 2 splits ----
    const int nbase = blockIdx.x * 128 + wid * 16;
    const int n0 = nbase + r;
    const int n1 = n0 + 8;
    uint32_t af[2][4];
    #pragma unroll
    for (int s = 0; s < 2; ++s) {
        af[s][0] = *(const uint32_t*)&g_as[s][n0 * KK + 2 * t];
        af[s][1] = *(const uint32_t*)&g_as[s][n1 * KK + 2 * t];
        af[s][2] = *(const uint32_t*)&g_as[s][n0 * KK + 2 * t + 8];
        af[s][3] = *(const uint32_t*)&g_as[s][n1 * KK + 2 * t + 8];
    }

    float best0 = -3.0e38f, sec0 = -3.0e38f;
    float best1 = -3.0e38f, sec1 = -3.0e38f;
    int   bi0 = 0, bi1 = 0;

    #pragma unroll 2
    for (int dtile = 0; dtile < DD / 8; ++dtile) {
        const int dg = dtile * 8;

        // B fragments: one LDS.64 per split (frag-packed layout)
        uint32_t bf[2][2];
        #pragma unroll
        for (int s = 0; s < 2; ++s) {
            const uint64_t q = *(const uint64_t*)(smem + s * (DD * KK * 2)
                                                  + (dg + r) * (KK * 2) + t * 8);
            bf[s][0] = (uint32_t)q;
            bf[s][1] = (uint32_t)(q >> 32);
        }

        // big term a1*b1; small terms a1*b2 + a2*b1 (same scale, one acc)
        float bA0 = 0.f, bA1 = 0.f, bA2 = 0.f, bA3 = 0.f;
        float sA0 = 0.f, sA1 = 0.f, sA2 = 0.f, sA3 = 0.f;
        mma16816(bA0, bA1, bA2, bA3, af[0][0], af[0][1], af[0][2], af[0][3],
                 bf[0][0], bf[0][1]);
        mma16816(sA0, sA1, sA2, sA3, af[0][0], af[0][1], af[0][2], af[0][3],
                 bf[1][0], bf[1][1]);
        mma16816(sA0, sA1, sA2, sA3, af[1][0], af[1][1], af[1][2], af[1][3],
                 bf[0][0], bf[0][1]);
        const float v0 = bA0 + sA0, v1 = bA1 + sA1;
        const float v2 = bA2 + sA2, v3 = bA3 + sA3;

        const int c0 = dg + 2 * t, c1 = c0 + 1;
        // branchless top-2 update, row n0
        {
            const float m01  = fmaxf(v0, v1);
            const float mn01 = fminf(v0, v1);
            const int   cm   = (v0 >= v1) ? c0 : c1;
            const bool  up   = m01 > best0;
            sec0  = up ? fmaxf(best0, mn01) : fmaxf(sec0, m01);
            bi0   = up ? cm : bi0;
            best0 = fmaxf(best0, m01);
        }
        // row n1
        {
            const float m01  = fmaxf(v2, v3);
            const float mn01 = fminf(v2, v3);
            const int   cm   = (v2 >= v3) ? c0 : c1;
            const bool  up   = m01 > best1;
            sec1  = up ? fmaxf(best1, mn01) : fmaxf(sec1, m01);
            bi1   = up ? cm : bi1;
            best1 = fmaxf(best1, m01);
        }
    }

    // ---- 4-lane butterfly reduce: (best desc, idx asc), track global second ----
    #pragma unroll
    for (int m = 1; m <= 2; m <<= 1) {
        float ob = __shfl_xor_sync(0xffffffffu, best0, m);
        float os = __shfl_xor_sync(0xffffffffu, sec0,  m);
        int   oi = __shfl_xor_sync(0xffffffffu, bi0,   m);
        float ns = fmaxf(fmaxf(fminf(best0, ob), sec0), os);
        if (ob > best0 || (ob == best0 && oi < bi0)) { best0 = ob; bi0 = oi; }
        sec0 = ns;

        ob = __shfl_xor_sync(0xffffffffu, best1, m);
        os = __shfl_xor_sync(0xffffffffu, sec1,  m);
        oi = __shfl_xor_sync(0xffffffffu, bi1,   m);
        ns = fmaxf(fmaxf(fminf(best1, ob), sec1), os);
        if (ob > best1 || (ob == best1 && oi < bi1)) { best1 = ob; bi1 = oi; }
        sec1 = ns;
    }

    if (t == 0) {
        out[n0] = (float)bi0;
        out[n1] = (float)bi1;
        if (best0 - sec0 < MARGIN) {       // ambiguous (incl. ties) -> rescue
            const int j = atomicAdd(&g_nflag, 1);
            g_flaglist[j] = n0;
        }
        if (best1 - sec1 < MARGIN) {
            const int j = atomicAdd(&g_nflag, 1);
            g_flaglist[j] = n1;
        }
    }
}

// ---------------- rescue v2: exact R5 chain on precomputed bnorm ----------------
__global__ __launch_bounds__(256) void rescue_kernel(
    const float* __restrict__ x,
    float* __restrict__ out)
{
    const int warp  = (blockIdx.x * 256 + threadIdx.x) >> 5;
    const int lane  = threadIdx.x & 31;
    const int nwarp = (gridDim.x * 256) >> 5;
    const int count = g_nflag;

    for (int i = warp; i < count; i += nwarp) {
        const int n = g_flaglist[i];

        // a-normalization: identical op chain to the rel_err==0 R5 kernel
        float a[KK];
        float s = 0.f;
        #pragma unroll
        for (int k = 0; k < KK; ++k) { a[k] = x[k * NTOT + n]; s += a[k]; }
        const float mu = s * (1.0f / KK);
        float ss = 0.f;
        #pragma unroll
        for (int k = 0; k < KK; ++k) { a[k] -= mu; ss += a[k] * a[k]; }
        const float inv = 1.0f / (sqrtf(ss) + 1e-10f);
        #pragma unroll
        for (int k = 0; k < KK; ++k) a[k] *= inv;

        float best = -3.0e38f;
        int   bi   = 0;
        #pragma unroll 2
        for (int d0 = 0; d0 < DD; d0 += 32) {
            const int d = d0 + lane;
            const float4* bp = (const float4*)(&g_bnorm[d * KK]);  // L2-resident
            const float4 q0 = bp[0], q1 = bp[1], q2 = bp[2], q3 = bp[3];
            float acc = 0.f;
            acc = fmaf(a[0],  q0.x, acc); acc = fmaf(a[1],  q0.y, acc);
            acc = fmaf(a[2],  q0.z, acc); acc = fmaf(a[3],  q0.w, acc);
            acc = fmaf(a[4],  q1.x, acc); acc = fmaf(a[5],  q1.y, acc);
            acc = fmaf(a[6],  q1.z, acc); acc = fmaf(a[7],  q1.w, acc);
            acc = fmaf(a[8],  q2.x, acc); acc = fmaf(a[9],  q2.y, acc);
            acc = fmaf(a[10], q2.z, acc); acc = fmaf(a[11], q2.w, acc);
            acc = fmaf(a[12], q3.x, acc); acc = fmaf(a[13], q3.y, acc);
            acc = fmaf(a[14], q3.z, acc); acc = fmaf(a[15], q3.w, acc);
            if (acc > best) { best = acc; bi = d; }   // ascending d per lane
        }
        // 32-lane reduce: (value desc, index asc) == first occurrence
        #pragma unroll
        for (int m = 16; m >= 1; m >>= 1) {
            const float ov = __shfl_xor_sync(0xffffffffu, best, m);
            const int   oi = __shfl_xor_sync(0xffffffffu, bi,   m);
            if (ov > best || (ov == best && oi < bi)) { best = ov; bi = oi; }
        }
        if (lane == 0) out[n] = (float)bi;
    }
}

extern "C" void kernel_launch(void* const* d_in, const int* in_sizes, int n_in,
                              void* d_out, int out_size)
{
    // Select inputs by element count — immune to metadata ordering.
    const float* x;
    const float* cmat;
    if (in_sizes[0] >= in_sizes[1]) {
        x    = (const float*)d_in[0];
        cmat = (const float*)d_in[1];
    } else {
        x    = (const float*)d_in[1];
        cmat = (const float*)d_in[0];
    }
    float* out = (float*)d_out;

    prep_b_kernel<<<DD / 256, 256>>>(cmat);
    prep_a_kernel<<<NTOT / 256, 256>>>(x);

    const int smem = 2 * DD * KK * 2;   // 64 KB
    cudaFuncSetAttribute(ncc_hmma_kernel,
                         cudaFuncAttributeMaxDynamicSharedMemorySize, smem);
    ncc_hmma_kernel<<<NBLK, TPB, smem>>>(out);

    rescue_kernel<<<256, 256>>>(x, out);
}